// round 3
// baseline (speedup 1.0000x reference)
#include <cuda_runtime.h>
#include <cuda_bf16.h>
#include <cstddef>

// GodelToposEngine: next = clamp(R @ prev, 0, 1), up to 20 steps.
// status: 1=PROVEN (next==prev), 2=GODEL (next==pprev, step>=2), 3=TIMEOUT.
// allclose: |a-b| <= atol + rtol*|b|, atol=1e-4, rtol=1e-5 (b = second arg).

#define NN 8192
#define MAXS 20
#define ATOL 1e-4f
#define RTOL 1e-5f

// Triple-buffered state vectors + control scalars (no allocation allowed).
__device__ float g_buf[3][NN];
__device__ int g_status;
__device__ int g_steps;
__device__ int g_final;   // which buffer holds the final state
__device__ int g_viol1;   // any element violates allclose(next, prev)
__device__ int g_viol2;   // any element violates allclose(next, pprev)

__global__ void __launch_bounds__(256) init_kernel(const float* __restrict__ sv) {
    int idx = blockIdx.x * 256 + threadIdx.x;   // grid 32x256 = 8192
    float v = sv[idx];
    g_buf[0][idx] = v;   // prev  for step 1
    g_buf[2][idx] = v;   // pprev for step 1
    if (idx == 0) {
        g_status = 0;
        g_steps = 0;
        g_final = 2;
        g_viol1 = 0;
        g_viol2 = 0;
    }
}

// One step: GEMV + clamp + convergence-violation flags.
// 512 blocks x 256 threads; each warp handles 2 adjacent rows (16 rows/block).
// 512 blocks fit in ONE wave (148 SMs x >=4 resident) -> no tail wave.
__global__ void __launch_bounds__(256) gemv_step(const float* __restrict__ R,
                                                 int pi, int ppi, int ni) {
    if (g_status != 0) return;   // frozen: skip all work

    __shared__ float4 xs[NN / 4];   // 32 KB: prev vector
    __shared__ int sv1, sv2;

    const int tid = threadIdx.x;
    if (tid == 0) { sv1 = 0; sv2 = 0; }

    const float4* pv = (const float4*)g_buf[pi];
#pragma unroll
    for (int i = 0; i < NN / 4 / 256; i++)
        xs[tid + 256 * i] = pv[tid + 256 * i];
    __syncthreads();

    const int warp = tid >> 5;
    const int lane = tid & 31;
    const int w    = blockIdx.x * 8 + warp;   // global warp id, [0, 4096)
    const int row0 = 2 * w;                   // rows row0, row0+1

    const float4* rp0 = (const float4*)(R + (size_t)row0 * NN);
    const float4* rp1 = rp0 + (NN / 4);

    float a0x = 0.f, a0y = 0.f, a0z = 0.f, a0w = 0.f;
    float a1x = 0.f, a1y = 0.f, a1z = 0.f, a1w = 0.f;
#pragma unroll 4
    for (int j = lane; j < NN / 4; j += 32) {
        float4 a0 = __ldcs(rp0 + j);   // streaming: don't thrash x out of L2
        float4 a1 = __ldcs(rp1 + j);
        float4 b  = xs[j];
        a0x += a0.x * b.x;  a0y += a0.y * b.y;
        a0z += a0.z * b.z;  a0w += a0.w * b.w;
        a1x += a1.x * b.x;  a1y += a1.y * b.y;
        a1z += a1.z * b.z;  a1w += a1.w * b.w;
    }
    float s0 = (a0x + a0y) + (a0z + a0w);
    float s1 = (a1x + a1y) + (a1z + a1w);
#pragma unroll
    for (int o = 16; o; o >>= 1) {
        s0 += __shfl_xor_sync(0xFFFFFFFFu, s0, o);
        s1 += __shfl_xor_sync(0xFFFFFFFFu, s1, o);
    }

    if (lane == 0) {
        float v0 = fminf(fmaxf(s0, 0.0f), 1.0f);
        float v1 = fminf(fmaxf(s1, 0.0f), 1.0f);
        g_buf[ni][row0]     = v0;
        g_buf[ni][row0 + 1] = v1;
        float p0  = g_buf[pi][row0],      p1  = g_buf[pi][row0 + 1];
        float pp0 = g_buf[ppi][row0],     pp1 = g_buf[ppi][row0 + 1];
        int bad1 = (fabsf(v0 - p0)  > ATOL + RTOL * fabsf(p0)) |
                   (fabsf(v1 - p1)  > ATOL + RTOL * fabsf(p1));
        int bad2 = (fabsf(v0 - pp0) > ATOL + RTOL * fabsf(pp0)) |
                   (fabsf(v1 - pp1) > ATOL + RTOL * fabsf(pp1));
        if (bad1) atomicOr(&sv1, 1);
        if (bad2) atomicOr(&sv2, 1);
    }
    __syncthreads();
    if (tid == 0) {
        if (sv1) atomicOr(&g_viol1, 1);
        if (sv2) atomicOr(&g_viol2, 1);
    }
}

// Per-step status update (frozen-carry semantics of the reference scan).
__global__ void update_step(int k, int ni) {
    if (g_status == 0) {
        g_steps = k;
        g_final = ni;
        if (g_viol1 == 0)                g_status = 1;  // PROVEN (priority)
        else if (k >= 2 && g_viol2 == 0) g_status = 2;  // GODEL
    }
    g_viol1 = 0;
    g_viol2 = 0;
}

__global__ void __launch_bounds__(256) final_kernel(float* __restrict__ out,
                                                    int out_size) {
    int idx = blockIdx.x * 256 + threadIdx.x;   // grid 32x256 = 8192
    int fi = g_final;
    if (idx < NN && idx < out_size) out[idx] = g_buf[fi][idx];
    if (idx == 0 && out_size >= NN + 2) {
        int st = g_status;
        out[NN]     = (float)(st == 0 ? 3 : st);   // TIMEOUT fixup
        out[NN + 1] = (float)g_steps;
    }
}

extern "C" void kernel_launch(void* const* d_in, const int* in_sizes, int n_in,
                              void* d_out, int out_size) {
    const float* R  = (const float*)d_in[0];
    const float* sv = (const float*)d_in[1];
    float* out = (float*)d_out;

    init_kernel<<<32, 256>>>(sv);
    for (int k = 1; k <= MAXS; k++) {
        int pi  = (k - 1) % 3;   // prev
        int ppi = (k + 1) % 3;   // pprev  ((k-2) mod 3, kept non-negative)
        int ni  = k % 3;         // next
        gemv_step<<<512, 256>>>(R, pi, ppi, ni);
        update_step<<<1, 1>>>(k, ni);
    }
    final_kernel<<<32, 256>>>(out, out_size);
}

// round 5
// speedup vs baseline: 1.2529x; 1.2529x over previous
#include <cuda_runtime.h>
#include <cuda_bf16.h>
#include <cstddef>

// GodelToposEngine: next = clamp(R @ prev, 0, 1), up to 20 steps.
// status: 1=PROVEN (next==prev), 2=GODEL (next==pprev, step>=2), 3=TIMEOUT.
// allclose: |a-b| <= atol + rtol*|b|, atol=1e-4, rtol=1e-5 (b = second arg).

#define NN 8192
#define MAXS 20
#define ATOL 1e-4f
#define RTOL 1e-5f

// Triple-buffered state vectors + control scalars (no allocation allowed).
__device__ float g_buf[3][NN];
__device__ int g_status;
__device__ int g_steps;
__device__ int g_final;   // which buffer holds the final state
__device__ int g_viol1;   // any element violates allclose(next, prev)
__device__ int g_viol2;   // any element violates allclose(next, pprev)

__global__ void __launch_bounds__(256) init_kernel(const float* __restrict__ sv) {
    int idx = blockIdx.x * 256 + threadIdx.x;   // grid 32x256 = 8192
    float v = sv[idx];
    g_buf[0][idx] = v;   // prev  for step 1
    g_buf[2][idx] = v;   // pprev for step 1
    if (idx == 0) {
        g_status = 0;
        g_steps = 0;
        g_final = 2;
        g_viol1 = 0;
        g_viol2 = 0;
    }
}

// One step: GEMV + clamp + convergence-violation flags.
// 1024 blocks x 256 threads, warp-per-row. NO shared memory: x (32 KB) is
// served from L1 (228 KB) via cached loads; R streamed with __ldcs so it
// doesn't evict x. launch_bounds(256,8) -> <=32 regs -> 8 blocks/SM ->
// capacity 1184 blocks: the whole 1024-block grid is ONE near-uniform wave.
__global__ void __launch_bounds__(256, 8) gemv_step(const float* __restrict__ R,
                                                    int pi, int ppi, int ni) {
    if (g_status != 0) return;   // frozen: skip all work

    const int tid  = threadIdx.x;
    const int warp = tid >> 5;
    const int lane = tid & 31;
    const int row  = blockIdx.x * 8 + warp;

    const float4* __restrict__ rp = (const float4*)(R + (size_t)row * NN);
    const float4* __restrict__ xp = (const float4*)g_buf[pi];

    float ax = 0.f, ay = 0.f, az = 0.f, aw = 0.f;
#pragma unroll 8
    for (int j = lane; j < NN / 4; j += 32) {
        float4 a = __ldcs(rp + j);   // stream R: evict-first, keep L1 for x
        float4 b = __ldg(xp + j);    // x: L1-resident after warm-up
        ax += a.x * b.x;
        ay += a.y * b.y;
        az += a.z * b.z;
        aw += a.w * b.w;
    }
    float s = (ax + ay) + (az + aw);
#pragma unroll
    for (int o = 16; o; o >>= 1) s += __shfl_xor_sync(0xFFFFFFFFu, s, o);

    if (lane == 0) {
        float v = fminf(fmaxf(s, 0.0f), 1.0f);
        g_buf[ni][row] = v;
        float p  = g_buf[pi][row];
        float pp = g_buf[ppi][row];
        if (fabsf(v - p)  > ATOL + RTOL * fabsf(p))  atomicOr(&g_viol1, 1);
        if (fabsf(v - pp) > ATOL + RTOL * fabsf(pp)) atomicOr(&g_viol2, 1);
    }
}

// Per-step status update (frozen-carry semantics of the reference scan).
__global__ void update_step(int k, int ni) {
    if (g_status == 0) {
        g_steps = k;
        g_final = ni;
        if (g_viol1 == 0)                g_status = 1;  // PROVEN (priority)
        else if (k >= 2 && g_viol2 == 0) g_status = 2;  // GODEL
    }
    g_viol1 = 0;
    g_viol2 = 0;
}

__global__ void __launch_bounds__(256) final_kernel(float* __restrict__ out,
                                                    int out_size) {
    int idx = blockIdx.x * 256 + threadIdx.x;   // grid 32x256 = 8192
    int fi = g_final;
    if (idx < NN && idx < out_size) out[idx] = g_buf[fi][idx];
    if (idx == 0 && out_size >= NN + 2) {
        int st = g_status;
        out[NN]     = (float)(st == 0 ? 3 : st);   // TIMEOUT fixup
        out[NN + 1] = (float)g_steps;
    }
}

extern "C" void kernel_launch(void* const* d_in, const int* in_sizes, int n_in,
                              void* d_out, int out_size) {
    const float* R  = (const float*)d_in[0];
    const float* sv = (const float*)d_in[1];
    float* out = (float*)d_out;

    init_kernel<<<32, 256>>>(sv);
    for (int k = 1; k <= MAXS; k++) {
        int pi  = (k - 1) % 3;   // prev
        int ppi = (k + 1) % 3;   // pprev  ((k-2) mod 3, kept non-negative)
        int ni  = k % 3;         // next
        gemv_step<<<1024, 256>>>(R, pi, ppi, ni);
        update_step<<<1, 1>>>(k, ni);
    }
    final_kernel<<<32, 256>>>(out, out_size);
}

// round 7
// speedup vs baseline: 1.3841x; 1.1047x over previous
#include <cuda_runtime.h>
#include <cuda_bf16.h>
#include <cstddef>
#include <cstdint>

// GodelToposEngine: next = clamp(R @ prev, 0, 1), up to 20 steps.
// status: 1=PROVEN (next==prev), 2=GODEL (next==pprev, step>=2), 3=TIMEOUT.
// allclose: |a-b| <= atol + rtol*|b|, atol=1e-4, rtol=1e-5 (b = second arg).

#define NN 8192
#define MAXS 20
#define ATOL 1e-4f
#define RTOL 1e-5f

#define CPS 256                 // columns per pipeline stage (floats)
#define NSTAGE (NN / CPS)       // 32 stages

// Triple-buffered state vectors + control scalars (no allocation allowed).
__device__ float g_buf[3][NN];
__device__ int g_status;
__device__ int g_steps;
__device__ int g_final;   // which buffer holds the final state
__device__ int g_viol1;   // any element violates allclose(next, prev)
__device__ int g_viol2;   // any element violates allclose(next, pprev)

__global__ void __launch_bounds__(256) init_kernel(const float* __restrict__ sv) {
    int idx = blockIdx.x * 256 + threadIdx.x;   // grid 32x256 = 8192
    float v = sv[idx];
    g_buf[0][idx] = v;   // prev  for step 1
    g_buf[2][idx] = v;   // pprev for step 1
    if (idx == 0) {
        g_status = 0;
        g_steps = 0;
        g_final = 2;
        g_viol1 = 0;
        g_viol2 = 0;
    }
}

__device__ __forceinline__ void cp16(uint32_t dst, const float* src) {
    // .cg: L2-only — keep L1 free for the x vector.
    asm volatile("cp.async.cg.shared.global [%0], [%1], 16;" :: "r"(dst), "l"(src));
}
__device__ __forceinline__ void cp_commit() {
    asm volatile("cp.async.commit_group;" ::: "memory");
}
__device__ __forceinline__ void cp_wait1() {
    asm volatile("cp.async.wait_group 1;" ::: "memory");
}

// One step: GEMV + clamp + convergence flags.
// 512 blocks x 256 threads; warp owns 2 adjacent rows. R is streamed into a
// per-warp double-buffered smem stage via cp.async (MLP decoupled from the
// register file). Each lane reads back only the smem bytes it itself copied,
// so the pipeline needs NO warp/block barriers — only cp.async.wait_group.
__global__ void __launch_bounds__(256, 4) gemv_step(const float* __restrict__ R,
                                                    int pi, int ppi, int ni) {
    if (g_status != 0) return;   // frozen: skip all work

    // [warp][slot][row][chunk] : 8*2*2*64 float4 = 32 KB
    __shared__ float4 smem[8][2][2][CPS / 4];

    const int tid  = threadIdx.x;
    const int warp = tid >> 5;
    const int lane = tid & 31;
    const int w    = blockIdx.x * 8 + warp;   // [0, 4096)
    const int row0 = 2 * w;

    const uint32_t sbase =
        (uint32_t)__cvta_generic_to_shared(&smem[warp][0][0][0]);
    const float* __restrict__ r0p = R + (size_t)row0 * NN;
    const float* __restrict__ r1p = r0p + NN;
    const float4* __restrict__ xp = (const float4*)g_buf[pi];

    // Prologue: stages 0 and 1 in flight.
#pragma unroll
    for (int s = 0; s < 2; s++) {
        uint32_t sb = sbase + (uint32_t)s * (2 * CPS * 4);
#pragma unroll
        for (int k = 0; k < 2; k++) {
            int c = lane + 32 * k;                       // chunk 0..63
            cp16(sb + c * 16,             r0p + s * CPS + c * 4);
            cp16(sb + CPS * 4 + c * 16,   r1p + s * CPS + c * 4);
        }
        cp_commit();
    }

    float a0x = 0.f, a0y = 0.f, a0z = 0.f, a0w = 0.f;
    float a1x = 0.f, a1y = 0.f, a1z = 0.f, a1w = 0.f;

#pragma unroll 1
    for (int s = 0; s < NSTAGE; s++) {
        cp_wait1();                      // stage s landed (<=1 group pending)
        const int slot = s & 1;
        const float4* sm = &smem[warp][slot][0][0];
#pragma unroll
        for (int k = 0; k < 2; k++) {
            int c = lane + 32 * k;
            float4 b  = __ldg(xp + s * (CPS / 4) + c);   // L1-resident x
            float4 a0 = sm[c];
            float4 a1 = sm[CPS / 4 + c];
            a0x += a0.x * b.x;  a0y += a0.y * b.y;
            a0z += a0.z * b.z;  a0w += a0.w * b.w;
            a1x += a1.x * b.x;  a1y += a1.y * b.y;
            a1z += a1.z * b.z;  a1w += a1.w * b.w;
        }
        // Refill this slot with stage s+2 (commit every iteration to keep
        // the one-group-per-iteration accounting exact).
        if (s + 2 < NSTAGE) {
            uint32_t sb = sbase + (uint32_t)slot * (2 * CPS * 4);
            int sc = (s + 2) * CPS;
#pragma unroll
            for (int k = 0; k < 2; k++) {
                int c = lane + 32 * k;
                cp16(sb + c * 16,           r0p + sc + c * 4);
                cp16(sb + CPS * 4 + c * 16, r1p + sc + c * 4);
            }
        }
        cp_commit();
    }

    float s0 = (a0x + a0y) + (a0z + a0w);
    float s1 = (a1x + a1y) + (a1z + a1w);
#pragma unroll
    for (int o = 16; o; o >>= 1) {
        s0 += __shfl_xor_sync(0xFFFFFFFFu, s0, o);
        s1 += __shfl_xor_sync(0xFFFFFFFFu, s1, o);
    }

    if (lane == 0) {
        float v0 = fminf(fmaxf(s0, 0.0f), 1.0f);
        float v1 = fminf(fmaxf(s1, 0.0f), 1.0f);
        g_buf[ni][row0]     = v0;
        g_buf[ni][row0 + 1] = v1;
        float p0  = g_buf[pi][row0],  p1  = g_buf[pi][row0 + 1];
        float pp0 = g_buf[ppi][row0], pp1 = g_buf[ppi][row0 + 1];
        int bad1 = (fabsf(v0 - p0)  > ATOL + RTOL * fabsf(p0)) |
                   (fabsf(v1 - p1)  > ATOL + RTOL * fabsf(p1));
        int bad2 = (fabsf(v0 - pp0) > ATOL + RTOL * fabsf(pp0)) |
                   (fabsf(v1 - pp1) > ATOL + RTOL * fabsf(pp1));
        if (bad1) atomicOr(&g_viol1, 1);
        if (bad2) atomicOr(&g_viol2, 1);
    }
}

// Per-step status update (frozen-carry semantics of the reference scan).
__global__ void update_step(int k, int ni) {
    if (g_status == 0) {
        g_steps = k;
        g_final = ni;
        if (g_viol1 == 0)                g_status = 1;  // PROVEN (priority)
        else if (k >= 2 && g_viol2 == 0) g_status = 2;  // GODEL
    }
    g_viol1 = 0;
    g_viol2 = 0;
}

__global__ void __launch_bounds__(256) final_kernel(float* __restrict__ out,
                                                    int out_size) {
    int idx = blockIdx.x * 256 + threadIdx.x;   // grid 32x256 = 8192
    int fi = g_final;
    if (idx < NN && idx < out_size) out[idx] = g_buf[fi][idx];
    if (idx == 0 && out_size >= NN + 2) {
        int st = g_status;
        out[NN]     = (float)(st == 0 ? 3 : st);   // TIMEOUT fixup
        out[NN + 1] = (float)g_steps;
    }
}

extern "C" void kernel_launch(void* const* d_in, const int* in_sizes, int n_in,
                              void* d_out, int out_size) {
    const float* R  = (const float*)d_in[0];
    const float* sv = (const float*)d_in[1];
    float* out = (float*)d_out;

    init_kernel<<<32, 256>>>(sv);
    for (int k = 1; k <= MAXS; k++) {
        int pi  = (k - 1) % 3;   // prev
        int ppi = (k + 1) % 3;   // pprev  ((k-2) mod 3, kept non-negative)
        int ni  = k % 3;         // next
        gemv_step<<<512, 256>>>(R, pi, ppi, ni);
        update_step<<<1, 1>>>(k, ni);
    }
    final_kernel<<<32, 256>>>(out, out_size);
}